// round 7
// baseline (speedup 1.0000x reference)
#include <cuda_runtime.h>
#include <cuda_bf16.h>
#include <cstdint>
#include <cstring>
#include <math.h>

#define NB 4096
#define NT 8192
#define DD 256
#define CC 31
#define TILES 64
#define NTILEPAIRS 2080

// ======================= device scratch =======================
__device__ float  g_sq[NT];
__device__ float  g_colpart[64][DD];
__device__ float  g_tpart[32][CC];
__device__ int    g_scnt_part[32][32];
__device__ int    g_tpres_part[32][32];
__device__ float  g_sScale[32];
__device__ float  g_tScale[32];
__device__ float  g_coef[5];
__device__ float  g_c0;
__device__ int    g_chain;
__device__ float  g_inv_nidx;
__device__ double g_loss;

__device__ __align__(16) unsigned short g_Xh[NT * DD];
__device__ __align__(16) unsigned short g_Xl[NT * DD];
__device__ __align__(16) unsigned short g_Vh[NT * 32];
__device__ __align__(16) unsigned short g_Vl[NT * 32];

// ======================= helpers =======================
__device__ __forceinline__ float ex2f(float x) {
    float y; asm("ex2.approx.ftz.f32 %0, %1;" : "=f"(y) : "f"(x)); return y;
}
__device__ __forceinline__ uint32_t smem_u32(const void* p) {
    uint32_t a;
    asm("{ .reg .u64 t; cvta.to.shared.u64 t, %1; cvt.u32.u64 %0, t; }" : "=r"(a) : "l"(p));
    return a;
}
#define CP16(dst, src) \
    asm volatile("cp.async.cg.shared.global [%0], [%1], 16;" :: "r"(dst), "l"(src))
#define CP_COMMIT() asm volatile("cp.async.commit_group;" ::: "memory")
#define CP_WAIT1()  asm volatile("cp.async.wait_group 1;" ::: "memory")
#define CP_WAIT0()  asm volatile("cp.async.wait_group 0;" ::: "memory")

__device__ __forceinline__ void ldsm4(uint32_t r[4], uint32_t addr) {
    asm volatile("ldmatrix.sync.aligned.m8n8.x4.shared.b16 {%0,%1,%2,%3}, [%4];"
        : "=r"(r[0]), "=r"(r[1]), "=r"(r[2]), "=r"(r[3]) : "r"(addr));
}
__device__ __forceinline__ void mma16816(float d[4], const uint32_t a[4], const uint32_t b[2]) {
    asm volatile("mma.sync.aligned.m16n8k16.row.col.f32.bf16.bf16.f32 "
        "{%0,%1,%2,%3}, {%4,%5,%6,%7}, {%8,%9}, {%0,%1,%2,%3};"
        : "+f"(d[0]), "+f"(d[1]), "+f"(d[2]), "+f"(d[3])
        : "r"(a[0]), "r"(a[1]), "r"(a[2]), "r"(a[3]), "r"(b[0]), "r"(b[1]));
}

// ======================= smem layout (k_main) =======================
// V: packed hi(segs 0-3)+lo(segs 4-7) per 128B row; VA then VB, 16KB each.
#define SM_VA   0
#define SM_VB   16384
#define SM_S0   32768
#define SM_S1   (32768 + 65536)
#define SM_S2   (32768 + 2 * 65536)
#define SM_SQA  229376
#define SM_SQB  229888
#define SM_RED  230400
#define SMEM_TOTAL 230464

// ======================= K1: fused prepass =======================
// 64 CTAs x 256 thr; CTA b owns rows [b*128, b*128+128) of the concatenated matrix.
__global__ void k_prep(const float* __restrict__ src, const float* __restrict__ tgt,
                       const int* __restrict__ s_label, const float* __restrict__ t_label) {
    __shared__ float sh_f[32];
    __shared__ int   sh_i[32];
    int b = blockIdx.x, t = threadIdx.x;
    int wid = t >> 5, lane = t & 31;
    int r0 = b * 128;
    const float* base = (b < 32) ? src + (size_t)r0 * DD : tgt + (size_t)(r0 - NB) * DD;

    // --- column sums (thread = column) ---
    float acc = 0.f;
    for (int r = 0; r < 128; r++) acc += base[(size_t)r * DD + t];
    g_colpart[b][t] = acc;

    // --- row squared norms (warp per row) ---
    for (int rr = wid; rr < 128; rr += 8) {
        const float* rp = base + (size_t)rr * DD;
        float s = 0.f;
        for (int k = lane; k < DD; k += 32) { float v = rp[k]; s = fmaf(v, v, s); }
#pragma unroll
        for (int off = 16; off; off >>= 1) s += __shfl_xor_sync(0xffffffffu, s, off);
        if (lane == 0) g_sq[r0 + rr] = s;
    }

    // --- bf16 hi/lo split ---
    for (int q = 0; q < 32; q++) {
        int idx = q * 256 + t;                       // 0..8191 float4s
        size_t e = (size_t)r0 * DD + (size_t)idx * 4;
        float4 x = *(const float4*)(base + (size_t)idx * 4);
        float xs[4] = {x.x, x.y, x.z, x.w};
        unsigned short h[4], l[4];
#pragma unroll
        for (int p = 0; p < 4; p++) {
            __nv_bfloat16 hb = __float2bfloat16(xs[p]);
            float rest = xs[p] - __bfloat162float(hb);
            __nv_bfloat16 lb = __float2bfloat16(rest);
            memcpy(&h[p], &hb, 2); memcpy(&l[p], &lb, 2);
        }
        *(uint2*)(g_Xh + e) = make_uint2((uint32_t)h[0] | ((uint32_t)h[1] << 16),
                                         (uint32_t)h[2] | ((uint32_t)h[3] << 16));
        *(uint2*)(g_Xl + e) = make_uint2((uint32_t)l[0] | ((uint32_t)l[1] << 16),
                                         (uint32_t)l[2] | ((uint32_t)l[3] << 16));
    }

    // --- label statistics (per-CTA partials, no global init needed) ---
    if (t < 32) { sh_f[t] = 0.f; sh_i[t] = 0; }
    __syncthreads();
    if (b < 32) {
        if (t < 128) {
            int lbl = s_label[r0 + t];
            if ((unsigned)lbl < CC) atomicAdd(&sh_i[lbl], 1);
        }
        __syncthreads();
        if (t < 32) g_scnt_part[b][t] = sh_i[t];
    } else {
        int tb = b - 32;
        if (t < 128) {
            const float* tr = t_label + (size_t)(tb * 128 + t) * CC;
            float best = -1e30f; int arg = 0;
#pragma unroll
            for (int c = 0; c < CC; c++) {
                float v = tr[c];
                if (v > best) { best = v; arg = c; }
                float s = v;
#pragma unroll
                for (int off = 16; off; off >>= 1) s += __shfl_xor_sync(0xffffffffu, s, off);
                if (lane == 0) atomicAdd(&sh_f[c], s);
            }
            atomicOr(&sh_i[arg], 1);
        }
        __syncthreads();
        if (t < 32) {
            if (t < CC) g_tpart[tb][t] = sh_f[t];
            g_tpres_part[tb][t] = sh_i[t];
        }
    }
}

// ======================= K2: finalize scalars =======================
__global__ void k_finalize() {
    __shared__ double red[256];
    __shared__ double sMSQ;
    int t = threadIdx.x;

    float m = 0.f;
    for (int b = 0; b < 64; b++) m += g_colpart[b][t];
    red[t] = (double)m * (double)m;
    __syncthreads();
    for (int off = 128; off; off >>= 1) { if (t < off) red[t] += red[t + off]; __syncthreads(); }
    if (t == 0) sMSQ = red[0];
    __syncthreads();

    double s1 = 0.0;
    for (int r = t; r < NT; r += 256) s1 += (double)g_sq[r];
    red[t] = s1;
    __syncthreads();
    for (int off = 128; off; off >>= 1) { if (t < off) red[t] += red[t + off]; __syncthreads(); }

    if (t == 0) {
        g_loss = 0.0;
        double S1 = red[0], MSQ = sMSQ;
        double sum_l2 = 2.0 * (double)NT * S1 - 2.0 * MSQ;
        double bw = sum_l2 / ((double)NT * (double)NT - (double)NT);
        if (bw < 1e-6) bw = 1e-6;
        bw *= 0.25;
        g_chain = (bw >= 1e-6) ? 1 : 0;
        const double L2E = 1.4426950408889634;
        for (int i = 0; i < 5; i++) {
            double den = bw * (double)(1 << i);
            if (den < 1e-6) den = 1e-6;
            g_coef[i] = (float)(L2E / den);
        }
        g_c0 = g_coef[4];
        int nidx = 0;
        for (int c = 0; c < CC; c++) {
            int cnt = 0, pres = 0;
            float tc = 0.f;
            for (int b = 0; b < 32; b++) {
                cnt += g_scnt_part[b][c];
                pres |= g_tpres_part[b][c];
                tc += g_tpart[b][c];
            }
            int msk = (cnt > 0) && pres;
            nidx += msk;
            g_sScale[c] = msk ? 1.0f / (float)cnt : 0.f;
            float tdiv = (tc == 0.f) ? 100.f : tc;
            g_tScale[c] = msk ? 1.0f / tdiv : 0.f;
        }
        g_sScale[31] = 0.f; g_tScale[31] = 0.f;
        if (nidx < 1) nidx = 1;
        g_inv_nidx = 1.0f / (float)nidx;
    }
}

// ======================= K3: build signed weight vectors =======================
__global__ void k_buildV(const int* __restrict__ s_label, const float* __restrict__ t_label) {
    int i = blockIdx.x * 256 + threadIdx.x;
    float v[32];
    if (i < NB) {
#pragma unroll
        for (int c = 0; c < 32; c++) v[c] = 0.f;
        int lbl = s_label[i];
        if ((unsigned)lbl < CC) v[lbl] = g_sScale[lbl];
    } else {
        const float* tr = t_label + (size_t)(i - NB) * CC;
#pragma unroll
        for (int c = 0; c < CC; c++) v[c] = -tr[c] * g_tScale[c];
        v[31] = 0.f;
    }
    unsigned short* vh = g_Vh + (size_t)i * 32;
    unsigned short* vl = g_Vl + (size_t)i * 32;
#pragma unroll
    for (int c = 0; c < 32; c++) {
        __nv_bfloat16 hb = __float2bfloat16(v[c]);
        float rest = v[c] - __bfloat162float(hb);
        __nv_bfloat16 lb = __float2bfloat16(rest);
        unsigned short hu, lu; memcpy(&hu, &hb, 2); memcpy(&lu, &lb, 2);
        vh[c] = hu; vl[c] = lu;
    }
}

// ======================= K4: main tile kernel =======================
__device__ __forceinline__ void issue_chunk(uint32_t sb, uint32_t stage,
        const unsigned short* Ah, const unsigned short* Al,
        const unsigned short* Bh, const unsigned short* Bl,
        int chunk, int tid) {
    const unsigned short* gp[4] = {Ah, Al, Bh, Bl};
#pragma unroll
    for (int t = 0; t < 4; t++) {
#pragma unroll
        for (int q = 0; q < 2; q++) {
            int idx = q * 512 + tid;
            int row = idx >> 3, c16 = idx & 7;
            const unsigned short* src = gp[t] + row * 256 + chunk * 64 + c16 * 8;
            uint32_t dst = sb + stage + t * 16384 + row * 128 + ((c16 ^ (row & 7)) << 4);
            CP16(dst, src);
        }
    }
}

// Gram: 3-product accumulation over 4 ksteps of 16.
__device__ __forceinline__ void do_mma(uint32_t aH, uint32_t aL, uint32_t bH, uint32_t bL,
                                       int wm, int wn, int lane, float acc[2][4][4]) {
    int r16 = lane & 15;
    int cuA = lane >> 4;
    int cuB = (lane >> 3) & 1;
    int jrow = (lane >> 4) * 8;
#pragma unroll
    for (int ks = 0; ks < 4; ks++) {
        uint32_t ah[2][4], al[2][4], bh[2][4], bl[2][4];
#pragma unroll
        for (int i = 0; i < 2; i++) {
            int row = wm * 32 + i * 16 + r16;
            uint32_t ro = (uint32_t)(row * 128 + (((ks * 2 + cuA) ^ (row & 7)) << 4));
            ldsm4(ah[i], aH + ro);
            ldsm4(al[i], aL + ro);
        }
#pragma unroll
        for (int p = 0; p < 2; p++) {
            int row = wn * 32 + p * 16 + jrow + (lane & 7);
            uint32_t ro = (uint32_t)(row * 128 + (((ks * 2 + cuB) ^ (row & 7)) << 4));
            ldsm4(bh[p], bH + ro);
            ldsm4(bl[p], bL + ro);
        }
#pragma unroll
        for (int i = 0; i < 2; i++)
#pragma unroll
            for (int j = 0; j < 4; j++) {
                const uint32_t* fh = &bh[j >> 1][(j & 1) * 2];
                const uint32_t* fl = &bl[j >> 1][(j & 1) * 2];
                mma16816(acc[i][j], ah[i], fh);
                mma16816(acc[i][j], ah[i], fl);
                mma16816(acc[i][j], al[i], fh);
            }
    }
}

// V (packed hi segs 0-3, lo segs 4-7): 3-product over 2 ksteps of 16.
__device__ __forceinline__ void do_mma_v(uint32_t vA, uint32_t vB,
                                         int wm, int wn, int lane, float acc[2][4][4]) {
    int r16 = lane & 15;
    int cuA = lane >> 4;
    int cuB = (lane >> 3) & 1;
    int jrow = (lane >> 4) * 8;
#pragma unroll
    for (int ks = 0; ks < 2; ks++) {
        uint32_t ah[2][4], al[2][4], bh[2][4], bl[2][4];
#pragma unroll
        for (int i = 0; i < 2; i++) {
            int row = wm * 32 + i * 16 + r16;
            uint32_t roh = (uint32_t)(row * 128 + (((ks * 2 + cuA) ^ (row & 7)) << 4));
            uint32_t rol = (uint32_t)(row * 128 + (((ks * 2 + cuA + 4) ^ (row & 7)) << 4));
            ldsm4(ah[i], vA + roh);
            ldsm4(al[i], vA + rol);
        }
#pragma unroll
        for (int p = 0; p < 2; p++) {
            int row = wn * 32 + p * 16 + jrow + (lane & 7);
            uint32_t roh = (uint32_t)(row * 128 + (((ks * 2 + cuB) ^ (row & 7)) << 4));
            uint32_t rol = (uint32_t)(row * 128 + (((ks * 2 + cuB + 4) ^ (row & 7)) << 4));
            ldsm4(bh[p], vB + roh);
            ldsm4(bl[p], vB + rol);
        }
#pragma unroll
        for (int i = 0; i < 2; i++)
#pragma unroll
            for (int j = 0; j < 4; j++) {
                const uint32_t* fh = &bh[j >> 1][(j & 1) * 2];
                const uint32_t* fl = &bl[j >> 1][(j & 1) * 2];
                mma16816(acc[i][j], ah[i], fh);
                mma16816(acc[i][j], ah[i], fl);
                mma16816(acc[i][j], al[i], fh);
            }
    }
}

__global__ void __launch_bounds__(512, 1) k_main() {
    extern __shared__ __align__(1024) char smem[];
    uint32_t sb = smem_u32(smem);
    int tid = threadIdx.x, wid = tid >> 5, lane = tid & 31;
    int wm = wid & 3, wn = wid >> 2;

    int bid = blockIdx.x, ti = 0, rem = bid;
    while (rem >= TILES - ti) { rem -= TILES - ti; ti++; }
    int tj = ti + rem;
    int rA = ti * 128, rB = tj * 128;

    float* ssqa = (float*)(smem + SM_SQA);
    float* ssqb = (float*)(smem + SM_SQB);
    float* sred = (float*)(smem + SM_RED);
    if (tid < 128) ssqa[tid] = g_sq[rA + tid];
    else if (tid < 256) ssqb[tid - 128] = g_sq[rB + tid - 128];

    const unsigned short* Ah = g_Xh + (size_t)rA * 256;
    const unsigned short* Al = g_Xl + (size_t)rA * 256;
    const unsigned short* Bh = g_Xh + (size_t)rB * 256;
    const unsigned short* Bl = g_Xl + (size_t)rB * 256;

    // group0: V (packed) + chunk0 -> s0
    {
        int row = tid >> 2, c16 = tid & 3;
        const unsigned short* vah = g_Vh + (size_t)rA * 32;
        const unsigned short* val = g_Vl + (size_t)rA * 32;
        const unsigned short* vbh = g_Vh + (size_t)rB * 32;
        const unsigned short* vbl = g_Vl + (size_t)rB * 32;
        uint32_t rb = sb + row * 128;
        CP16(rb + SM_VA + ((c16 ^ (row & 7)) << 4),        vah + row * 32 + c16 * 8);
        CP16(rb + SM_VA + (((c16 + 4) ^ (row & 7)) << 4),  val + row * 32 + c16 * 8);
        CP16(rb + SM_VB + ((c16 ^ (row & 7)) << 4),        vbh + row * 32 + c16 * 8);
        CP16(rb + SM_VB + (((c16 + 4) ^ (row & 7)) << 4),  vbl + row * 32 + c16 * 8);
        issue_chunk(sb, SM_S0, Ah, Al, Bh, Bl, 0, tid);
        CP_COMMIT();
    }
    // group1: chunk1 -> s1
    issue_chunk(sb, SM_S1, Ah, Al, Bh, Bl, 1, tid);
    CP_COMMIT();

    float acc[2][4][4], wacc[2][4][4];
#pragma unroll
    for (int i = 0; i < 2; i++)
#pragma unroll
        for (int j = 0; j < 4; j++)
#pragma unroll
            for (int r = 0; r < 4; r++) { acc[i][j][r] = 0.f; wacc[i][j][r] = 0.f; }

    const uint32_t stg[3] = {sb + SM_S0, sb + SM_S1, sb + SM_S2};
#pragma unroll 1
    for (int c = 0; c < 4; c++) {
        if (c < 3) { CP_WAIT1(); } else { CP_WAIT0(); }
        __syncthreads();
        if (c < 2) {
            issue_chunk(sb, (c == 0) ? SM_S2 : SM_S0, Ah, Al, Bh, Bl, c + 2, tid);
            CP_COMMIT();
        }
        uint32_t st = stg[c % 3];
        do_mma(st, st + 16384, st + 32768, st + 49152, wm, wn, lane, acc);
    }

    // W = Va . Vb^T
    do_mma_v(sb + SM_VA, sb + SM_VB, wm, wn, lane, wacc);

    // ---- epilogue ----
    float sqa_r[4], sqb_c[8];
#pragma unroll
    for (int i = 0; i < 2; i++)
#pragma unroll
        for (int rh = 0; rh < 2; rh++)
            sqa_r[i * 2 + rh] = ssqa[wm * 32 + i * 16 + (lane >> 2) + rh * 8];
#pragma unroll
    for (int j = 0; j < 4; j++)
#pragma unroll
        for (int cc2 = 0; cc2 < 2; cc2++)
            sqb_c[j * 2 + cc2] = ssqb[wn * 32 + j * 8 + (lane & 3) * 2 + cc2];

    float c0 = g_c0;
    int chain = g_chain;
    float cf0 = 0, cf1 = 0, cf2 = 0, cf3 = 0, cf4 = 0;
    if (!chain) { cf0 = g_coef[0]; cf1 = g_coef[1]; cf2 = g_coef[2]; cf3 = g_coef[3]; cf4 = g_coef[4]; }

    float part = 0.f;
#pragma unroll
    for (int i = 0; i < 2; i++)
#pragma unroll
        for (int j = 0; j < 4; j++)
#pragma unroll
            for (int r = 0; r < 4; r++) {
                float l2 = fmaf(-2.0f, acc[i][j][r], sqa_r[i * 2 + (r >> 1)] + sqb_c[j * 2 + (r & 1)]);
                l2 = fmaxf(l2, 0.0f);
                float ks;
                if (chain) {
                    float x  = ex2f(-l2 * c0);
                    float x2 = x * x, x4 = x2 * x2, x8 = x4 * x4;
                    ks = x + x2 + x4 + x8 + x8 * x8;
                } else {
                    ks = ex2f(-l2 * cf0) + ex2f(-l2 * cf1) + ex2f(-l2 * cf2)
                       + ex2f(-l2 * cf3) + ex2f(-l2 * cf4);
                }
                part = fmaf(ks, wacc[i][j][r], part);
            }
    if (ti != tj) part *= 2.0f;

#pragma unroll
    for (int off = 16; off; off >>= 1) part += __shfl_xor_sync(0xffffffffu, part, off);
    if (lane == 0) sred[wid] = part;
    __syncthreads();
    if (tid == 0) {
        float s = 0.f;
#pragma unroll
        for (int w = 0; w < 16; w++) s += sred[w];
        atomicAdd(&g_loss, (double)s);
    }
}

__global__ void k_out(float* out) {
    out[0] = (float)(g_loss * (double)g_inv_nidx);
}

// ======================= launch =======================
extern "C" void kernel_launch(void* const* d_in, const int* in_sizes, int n_in,
                              void* d_out, int out_size) {
    const float* src = (const float*)d_in[0];
    const float* tgt = (const float*)d_in[1];
    const int*   sl  = (const int*)d_in[2];
    const float* tl  = (const float*)d_in[3];
    float* out = (float*)d_out;

    cudaFuncSetAttribute(k_main, cudaFuncAttributeMaxDynamicSharedMemorySize, SMEM_TOTAL);

    k_prep<<<64, 256>>>(src, tgt, sl, tl);
    k_finalize<<<1, 256>>>();
    k_buildV<<<32, 256>>>(sl, tl);
    k_main<<<NTILEPAIRS, 512, SMEM_TOTAL>>>();
    k_out<<<1, 1>>>(out);
}